// round 6
// baseline (speedup 1.0000x reference)
#include <cuda_runtime.h>
#include <cuda_fp16.h>
#include <cstdint>

#define Nn 100000
#define Mm 800000
#define FIN 64
#define FE  16
#define HH  64
#define CAP 48

// ---------------- device scratch (no allocations allowed) ----------------
__device__ __half  g_h2h[(size_t)Nn * 64];    // h2 rows fp16 (128B/row)
__device__ float4  g_aggE[Nn * 12];           // aggregated edge_feat [N][3][16]
__device__ float   g_cntE[Nn * 3];            // per (dst, etype) counts
__device__ int     g_cur[Nn];                 // bucket cursors
__device__ int     g_slots[(size_t)Nn * CAP]; // bucket payload: src per incident edge
__device__ int     g_idx[2][Nn];              // per-type node lists
__device__ int     g_tcnt[2];
__device__ int     g_ovf_cnt;
__device__ int2    g_ovf[8192];               // overflow edges (src,dst)

__device__ __forceinline__ void red_add_f4(float4* p, float4 v) {
    asm volatile("red.global.add.v4.f32 [%0], {%1,%2,%3,%4};"
                 :: "l"(p), "f"(v.x), "f"(v.y), "f"(v.z), "f"(v.w)
                 : "memory");
}

__device__ __forceinline__ void mma_f16(float c[4], uint32_t a0, uint32_t a1,
                                        uint32_t a2, uint32_t a3,
                                        uint32_t b0, uint32_t b1) {
    asm volatile(
        "mma.sync.aligned.m16n8k16.row.col.f32.f16.f16.f32 "
        "{%0,%1,%2,%3},{%4,%5,%6,%7},{%8,%9},{%0,%1,%2,%3};"
        : "+f"(c[0]), "+f"(c[1]), "+f"(c[2]), "+f"(c[3])
        : "r"(a0), "r"(a1), "r"(a2), "r"(a3), "r"(b0), "r"(b1));
}

__device__ __forceinline__ uint32_t pack_h2(float a, float b) {
    __half2 h = __floats2half2_rn(a, b);
    return *(uint32_t*)&h;
}

// ---------------- kernels ----------------

__global__ void zero_kernel() {
    int gid = blockIdx.x * blockDim.x + threadIdx.x;
    int stride = gridDim.x * blockDim.x;
    float4 z = make_float4(0.f, 0.f, 0.f, 0.f);
    for (int i = gid; i < Nn * 12; i += stride) g_aggE[i] = z;
    for (int i = gid; i < Nn * 3; i += stride) g_cntE[i] = 0.f;
    for (int i = gid; i < Nn; i += stride) g_cur[i] = 0;
    if (gid < 2) g_tcnt[gid] = 0;
    if (gid == 2) g_ovf_cnt = 0;
}

// 4 threads/edge: scatter-add ef into aggE[dst][etype]; fused count + bucket fill
__global__ void edge_scatter_kernel(const float* __restrict__ ef,
                                    const int* __restrict__ esrc,
                                    const int* __restrict__ edst,
                                    const int* __restrict__ etype) {
    int gid = blockIdx.x * blockDim.x + threadIdx.x;
    int e = gid >> 2, q = gid & 3;
    if (e >= Mm) return;
    int dst = edst[e];
    int t   = etype[e];
    float4 v = ((const float4*)ef)[e * 4 + q];
    red_add_f4(&g_aggE[dst * 12 + t * 4 + q], v);
    if (q == 0) {
        atomicAdd(&g_cntE[dst * 3 + t], 1.0f);
        int src = esrc[e];
        int p = atomicAdd(&g_cur[dst], 1);
        if (p < CAP) {
            g_slots[(size_t)dst * CAP + p] = src;
        } else {
            int o = atomicAdd(&g_ovf_cnt, 1);
            if (o < 8192) g_ovf[o] = make_int2(src, dst);
        }
    }
}

// warp-aggregated partition by node type (2 atomics per warp)
__global__ void partition_kernel(const int* __restrict__ ntype) {
    const unsigned FULL = 0xffffffffu;
    int i = blockIdx.x * blockDim.x + threadIdx.x;
    int lane = threadIdx.x & 31;
    bool valid = (i < Nn);
    int t = valid ? ntype[i] : -1;
    unsigned m0 = __ballot_sync(FULL, t == 0);
    unsigned m1 = __ballot_sync(FULL, t == 1);
    int base0 = 0, base1 = 0;
    if (lane == 0) {
        if (m0) base0 = atomicAdd(&g_tcnt[0], __popc(m0));
        if (m1) base1 = atomicAdd(&g_tcnt[1], __popc(m1));
    }
    base0 = __shfl_sync(FULL, base0, 0);
    base1 = __shfl_sync(FULL, base1, 0);
    unsigned lt = (1u << lane) - 1u;
    if (t == 0) g_idx[0][base0 + __popc(m0 & lt)] = i;
    else if (t == 1) g_idx[1][base1 + __popc(m1 & lt)] = i;
}

// Persistent node GEMM (fp16 m16n8k16), 256 threads, 2 blocks/SM, tile M=64.
// A[64 x 128] = [x(64) | aggE(48) | cnt(3) | 0(13)] fp16, xs2[row][k2] stride 68.
// B[128 x 128] = [[W1|W2],[W5|0],[b5|0],[0|0]] per type, stored in smem in
// FRAGMENT ORDER: Wf[cg][kb][ntp][lane] = uint4{b0(nt0),b1(nt0),b0(nt1),b1(nt1)}
// so each warp's B operands per k-step are 4x LDS.128 (conflict-free).
// Output cols 0..63 -> out (fp32, h1+agg+b1); cols 64..127 -> g_h2h (fp16).
#define XSTR 68
__global__ __launch_bounds__(256, 2)
void node_gemm_kernel(const float* __restrict__ x,
                      const float* __restrict__ W1, const float* __restrict__ b1,
                      const float* __restrict__ W2, const float* __restrict__ b2,
                      const float* __restrict__ W5, const float* __restrict__ b5,
                      float* __restrict__ out) {
    extern __shared__ uint32_t smu[];
    uint4* Wf = (uint4*)smu;                 // [2][8][4][32] uint4 = 8192 words
    uint32_t* xs2 = smu + 8192;              // [64][68] half2 words
    float* bc = (float*)(xs2 + 64 * XSTR);   // [128]
    int* sidx = (int*)(bc + 128);            // [64]

    const int tid = threadIdx.x;
    const int w = tid >> 5, lane = tid & 31;
    const int g = lane >> 2, tq = lane & 3;
    const int rbase = (w & 3) * 16;          // 4 row groups
    const int cg = w >> 2;                   // 2 col groups
    const int cbase = cg * 64;
    const int r = tid >> 2, sub = tid & 3;

    const int c0n = g_tcnt[0];
    const int tiles0 = (c0n + 63) >> 6;
    const int c1n = Nn - c0n;
    const int tiles1 = (c1n + 63) >> 6;
    const int total = tiles0 + tiles1;

    // zero A tile once (pad k2 58..67 stays zero)
    for (int i = tid; i < 64 * XSTR; i += 256) xs2[i] = 0;

    // register staging (half2-packed at load time)
    uint2 hx[4], ha[3];
    uint32_t hcnt01 = 0, hcnt2 = 0;
    int snode = -1;

    auto stage_load = [&](int tile) {
        int typ = (tile < tiles0) ? 0 : 1;
        const int* list = g_idx[typ];
        int base = ((typ == 0) ? tile : (tile - tiles0)) << 6;
        int cnt = (typ == 0) ? c0n : c1n;
        int j = base + r;
        snode = (j < cnt) ? list[j] : -1;
        if (snode >= 0) {
            const float4* x4 = (const float4*)x;
            #pragma unroll
            for (int ii = 0; ii < 4; ii++) {
                float4 v = x4[snode * 16 + sub + 4 * ii];
                hx[ii] = make_uint2(pack_h2(v.x, v.y), pack_h2(v.z, v.w));
            }
            #pragma unroll
            for (int ii = 0; ii < 3; ii++) {
                float4 v = g_aggE[snode * 12 + sub + 4 * ii];
                ha[ii] = make_uint2(pack_h2(v.x, v.y), pack_h2(v.z, v.w));
            }
            if (sub == 0) {
                float c0 = g_cntE[snode * 3 + 0];
                float c1 = g_cntE[snode * 3 + 1];
                float c2 = g_cntE[snode * 3 + 2];
                hcnt01 = pack_h2(c0, c1);
                hcnt2 = pack_h2(c2, 0.f);
            }
        } else {
            uint2 z = make_uint2(0u, 0u);
            #pragma unroll
            for (int ii = 0; ii < 4; ii++) hx[ii] = z;
            #pragma unroll
            for (int ii = 0; ii < 3; ii++) ha[ii] = z;
            hcnt01 = 0; hcnt2 = 0;
        }
    };

    auto stage_store = [&]() {
        uint32_t* row = xs2 + r * XSTR;
        #pragma unroll
        for (int ii = 0; ii < 4; ii++)
            *(uint2*)(row + 8 * ii + 2 * sub) = hx[ii];
        #pragma unroll
        for (int ii = 0; ii < 3; ii++)
            *(uint2*)(row + 32 + 8 * ii + 2 * sub) = ha[ii];
        if (sub == 0) {
            row[56] = hcnt01;
            row[57] = hcnt2;
            sidx[r] = snode;
        }
    };

    int cur_typ = -1;
    int t_first = blockIdx.x;
    if (t_first < total) stage_load(t_first);

    for (int tile = blockIdx.x; tile < total; tile += gridDim.x) {
        int typ = (tile < tiles0) ? 0 : 1;
        __syncthreads();   // prior tile's readers done / zero-init done

        if (typ != cur_typ) {
            cur_typ = typ;
            const float* W1t = W1 + typ * (FIN * HH);
            const float* W2t = W2 + typ * (FIN * HH);
            auto w_src = [&](int kk, int c) -> float {
                float v = 0.f;
                if (kk < 64) v = (c < 64) ? W1t[kk * 64 + c] : W2t[kk * 64 + (c - 64)];
                else if (kk < 112) { if (c < 64) v = W5[(kk - 64) * 64 + c]; }
                else if (kk < 115) { if (c < 64) v = b5[(kk - 112) * 64 + c]; }
                return v;
            };
            // fragment-order fill: idx -> (cgf, kb, ntp, lane)
            for (int idx = tid; idx < 2048; idx += 256) {
                int ln = idx & 31;
                int ntp = (idx >> 5) & 3;
                int kb = (idx >> 7) & 7;
                int cgf = idx >> 10;
                int tqf = ln & 3, gf = ln >> 2;
                int k2a = kb * 8 + tqf;        // b0 k2
                int k2b = kb * 8 + tqf + 4;    // b1 k2
                int col0 = cgf * 64 + (2 * ntp) * 8 + gf;
                int col1 = cgf * 64 + (2 * ntp + 1) * 8 + gf;
                uint4 wv;
                wv.x = pack_h2(w_src(2 * k2a, col0), w_src(2 * k2a + 1, col0));
                wv.y = pack_h2(w_src(2 * k2b, col0), w_src(2 * k2b + 1, col0));
                wv.z = pack_h2(w_src(2 * k2a, col1), w_src(2 * k2a + 1, col1));
                wv.w = pack_h2(w_src(2 * k2b, col1), w_src(2 * k2b + 1, col1));
                Wf[idx] = wv;
            }
            if (tid < 128)
                bc[tid] = (tid < 64) ? b1[typ * 64 + tid] : b2[typ * 64 + (tid - 64)];
        }

        stage_store();
        __syncthreads();

        int next = tile + gridDim.x;
        if (next < total) stage_load(next);   // LDGs overlap MMA below

        float acc[8][4];
        #pragma unroll
        for (int nt = 0; nt < 8; nt++)
            #pragma unroll
            for (int j = 0; j < 4; j++) acc[nt][j] = 0.f;

        const uint4* Wfw = Wf + cg * 1024;    // this warp's col-group
        #pragma unroll
        for (int kb = 0; kb < 8; kb++) {
            int kb2 = kb * 8;
            uint32_t a0 = xs2[(rbase + g) * XSTR + kb2 + tq];
            uint32_t a1 = xs2[(rbase + g + 8) * XSTR + kb2 + tq];
            uint32_t a2 = xs2[(rbase + g) * XSTR + kb2 + tq + 4];
            uint32_t a3 = xs2[(rbase + g + 8) * XSTR + kb2 + tq + 4];
            #pragma unroll
            for (int ntp = 0; ntp < 4; ntp++) {
                uint4 bw = Wfw[(kb * 4 + ntp) * 32 + lane];
                mma_f16(acc[2 * ntp], a0, a1, a2, a3, bw.x, bw.y);
                mma_f16(acc[2 * ntp + 1], a0, a1, a2, a3, bw.z, bw.w);
            }
        }

        __half2* h2p = (__half2*)g_h2h;
        float2* outp = (float2*)out;
        #pragma unroll
        for (int nt = 0; nt < 8; nt++) {
            int col0 = cbase + nt * 8 + 2 * tq;
            float bcv0 = bc[col0], bcv1 = bc[col0 + 1];
            #pragma unroll
            for (int half_r = 0; half_r < 2; half_r++) {
                int rr = rbase + g + half_r * 8;
                int node = sidx[rr];
                if (node < 0) continue;
                float v0 = acc[nt][half_r * 2 + 0] + bcv0;
                float v1 = acc[nt][half_r * 2 + 1] + bcv1;
                if (col0 < 64) {
                    outp[node * 32 + (col0 >> 1)] = make_float2(v0, v1);
                } else {
                    h2p[node * 32 + ((col0 - 64) >> 1)] = __floats2half2_rn(v0, v1);
                }
            }
        }
    }
}

// Bucket gather: out[dst] += sum_{incident} h2[src]; 16 lanes per node
__global__ __launch_bounds__(256)
void h2_gather_kernel(float* __restrict__ out) {
    int tid = threadIdx.x;
    int node = blockIdx.x * 16 + (tid >> 4);
    int q = tid & 15;
    if (node >= Nn) return;
    int deg = g_cur[node];
    if (deg > CAP) deg = CAP;
    if (deg == 0) return;

    const uint2* H = (const uint2*)g_h2h;
    const int* sl = &g_slots[(size_t)node * CAP];
    float4 acc = make_float4(0.f, 0.f, 0.f, 0.f);

    auto add4 = [&](uint2 hv) {
        float2 f0 = __half22float2(*(__half2*)&hv.x);
        float2 f1 = __half22float2(*(__half2*)&hv.y);
        acc.x += f0.x; acc.y += f0.y; acc.z += f1.x; acc.w += f1.y;
    };

    int i = 0;
    for (; i + 4 <= deg; i += 4) {
        int s0 = __ldg(&sl[i]);
        int s1 = __ldg(&sl[i + 1]);
        int s2 = __ldg(&sl[i + 2]);
        int s3 = __ldg(&sl[i + 3]);
        uint2 v0 = __ldg(&H[s0 * 16 + q]);
        uint2 v1 = __ldg(&H[s1 * 16 + q]);
        uint2 v2 = __ldg(&H[s2 * 16 + q]);
        uint2 v3 = __ldg(&H[s3 * 16 + q]);
        add4(v0); add4(v1); add4(v2); add4(v3);
    }
    for (; i < deg; i++) add4(__ldg(&H[__ldg(&sl[i]) * 16 + q]));

    float4* o4 = (float4*)out;
    float4 o = o4[node * 16 + q];
    o.x += acc.x; o.y += acc.y; o.z += acc.z; o.w += acc.w;
    o4[node * 16 + q] = o;
}

// Rare overflow edges (deg > CAP): atomic scatter
__global__ void ovf_kernel(float4* __restrict__ out) {
    int n = g_ovf_cnt;
    if (n > 8192) n = 8192;
    int stride = gridDim.x * blockDim.x;
    for (int i = blockIdx.x * blockDim.x + threadIdx.x; i < n * 16; i += stride) {
        int e = i >> 4, q = i & 15;
        int2 sd = g_ovf[e];
        uint2 hv = ((const uint2*)g_h2h)[sd.x * 16 + q];
        float2 f0 = __half22float2(*(__half2*)&hv.x);
        float2 f1 = __half22float2(*(__half2*)&hv.y);
        red_add_f4(&out[sd.y * 16 + q], make_float4(f0.x, f0.y, f1.x, f1.y));
    }
}

// ---------------- launch ----------------
extern "C" void kernel_launch(void* const* d_in, const int* in_sizes, int n_in,
                              void* d_out, int out_size) {
    const float *x = nullptr, *ef = nullptr;
    const float *W[4] = {nullptr, nullptr, nullptr, nullptr};
    const float *B[4] = {nullptr, nullptr, nullptr, nullptr};
    const float *W5 = nullptr, *b5 = nullptr;
    const int *ntype = nullptr, *esrc = nullptr, *edst = nullptr, *etype = nullptr;
    int wI = 0, bI = 0, mI = 0;
    for (int i = 0; i < n_in; i++) {
        long s = in_sizes[i];
        const void* p = d_in[i];
        if (s == (long)Nn * FIN)      x = (const float*)p;
        else if (s == (long)Mm * FE)  ef = (const float*)p;
        else if (s == Nn)             ntype = (const int*)p;
        else if (s == Mm) {
            if (mI == 0) esrc = (const int*)p;
            else if (mI == 1) edst = (const int*)p;
            else etype = (const int*)p;
            mI++;
        }
        else if (s == 2 * FIN * HH) { if (wI < 4) W[wI++] = (const float*)p; }
        else if (s == 2 * HH)       { if (bI < 4) B[bI++] = (const float*)p; }
        else if (s == 3 * FE * HH)  W5 = (const float*)p;
        else if (s == 3 * HH)       b5 = (const float*)p;
    }
    float* out = (float*)d_out;

    const int smem_bytes = (8192 + 64 * XSTR + 128) * 4 + 64 * 4;
    cudaFuncSetAttribute(node_gemm_kernel,
                         cudaFuncAttributeMaxDynamicSharedMemorySize, 64 * 1024);

    zero_kernel<<<2048, 256>>>();
    edge_scatter_kernel<<<(Mm * 4 + 255) / 256, 256>>>(ef, esrc, edst, etype);
    partition_kernel<<<(Nn + 255) / 256, 256>>>(ntype);
    node_gemm_kernel<<<296, 256, smem_bytes>>>(
        x, W[0], B[0], W[1], B[1], W5, b5, out);
    h2_gather_kernel<<<(Nn + 15) / 16, 256>>>(out);
    ovf_kernel<<<16, 256>>>((float4*)out);
}